// round 2
// baseline (speedup 1.0000x reference)
#include <cuda_runtime.h>
#include <cstdint>

#define N_NODES  131072
#define N_EDGES  2097152
#define F_IN     32
#define HID      64
#define G_FEAT   16
#define N_GRAPHS 1024
#define BN_EPS   1e-5f

// ---------------- device scratch ----------------
__device__ int   g_degi[N_NODES];
__device__ int   g_rowstart[N_NODES];
__device__ int   g_fill[N_NODES];
__device__ int   g_srt[N_EDGES];
__device__ float g_dinv[N_NODES];
__device__ float g_y[(size_t)N_NODES * HID];
__device__ float g_z[(size_t)N_NODES * HID];
__device__ float g_bnsum[HID];
__device__ float g_bnsumsq[HID];
__device__ float g_scale[HID];
__device__ float g_shift[HID];
__device__ int   g_cnt[N_GRAPHS];
__device__ int   g_start[N_GRAPHS];
__device__ float g_pooled[(size_t)N_GRAPHS * HID];

// ---------------- init ----------------
__global__ void zero_kernel() {
    int t = blockIdx.x * 256 + threadIdx.x;
    if (t < N_NODES) g_degi[t] = 0;
    if (t < HID) { g_bnsum[t] = 0.f; g_bnsumsq[t] = 0.f; }
    if (t < N_GRAPHS) g_cnt[t] = 0;
}

// ---------------- degree (in-degree of dst) ----------------
__global__ void deg_kernel(const int* __restrict__ ei) {
    int e = blockIdx.x * 256 + threadIdx.x;
    if (e < N_EDGES) {
        int d = __ldg(ei + N_EDGES + e);
        unsigned one = 1u;
        asm volatile("red.global.add.u32 [%0], %1;" :: "l"((unsigned*)(g_degi + d)), "r"(one) : "memory");
    }
}

__global__ void dinv_kernel() {
    int n = blockIdx.x * 256 + threadIdx.x;
    if (n < N_NODES) g_dinv[n] = rsqrtf((float)g_degi[n] + 1.0f);
}

// ---------------- exclusive scan of degrees -> rowstart, fill ----------------
__global__ __launch_bounds__(1024) void scan_kernel() {
    __shared__ int sh[1024];
    int t = threadIdx.x;
    int base = t * 128;
    int sum = 0;
#pragma unroll 8
    for (int i = 0; i < 128; i++) sum += g_degi[base + i];
    sh[t] = sum;
    __syncthreads();
    for (int off = 1; off < 1024; off <<= 1) {
        int v = (t >= off) ? sh[t - off] : 0;
        __syncthreads();
        sh[t] += v;
        __syncthreads();
    }
    int run = sh[t] - sum;  // exclusive prefix of this thread's chunk
    for (int i = 0; i < 128; i++) {
        int d = g_degi[base + i];
        g_rowstart[base + i] = run;
        g_fill[base + i] = run;
        run += d;
    }
}

// ---------------- bucket edges by dst ----------------
__global__ void bucket_kernel(const int* __restrict__ ei) {
    int e = blockIdx.x * 256 + threadIdx.x;
    if (e < N_EDGES) {
        int src = __ldg(ei + e);
        int dst = __ldg(ei + N_EDGES + e);
        int pos = atomicAdd(&g_fill[dst], 1);
        g_srt[pos] = src;
    }
}

// ---------------- y = (in @ W) * dinv  (optionally affine+relu on input) ----------------
template <int K, bool AFFINE>
__global__ __launch_bounds__(128) void xw_kernel(const float* __restrict__ xin,
                                                 const float* __restrict__ W) {
    __shared__ float sW[K * HID];
    __shared__ float ssc[HID], ssh[HID];
    for (int i = threadIdx.x; i < K * HID; i += 128) sW[i] = W[i];
    if (AFFINE && threadIdx.x < HID) {
        ssc[threadIdx.x] = g_scale[threadIdx.x];
        ssh[threadIdx.x] = g_shift[threadIdx.x];
    }
    __syncthreads();
    int n = blockIdx.x * 128 + threadIdx.x;
    float in[K];
    if (!AFFINE) {
        const float4* r = (const float4*)(xin + (size_t)n * K);
#pragma unroll
        for (int k = 0; k < K / 4; k++) {
            float4 v = __ldg(r + k);
            in[4 * k + 0] = v.x; in[4 * k + 1] = v.y;
            in[4 * k + 2] = v.z; in[4 * k + 3] = v.w;
        }
    } else {
        const float4* r = (const float4*)(g_z + (size_t)n * HID);
#pragma unroll
        for (int k = 0; k < K / 4; k++) {
            float4 v = r[k];
            in[4 * k + 0] = fmaxf(v.x * ssc[4 * k + 0] + ssh[4 * k + 0], 0.f);
            in[4 * k + 1] = fmaxf(v.y * ssc[4 * k + 1] + ssh[4 * k + 1], 0.f);
            in[4 * k + 2] = fmaxf(v.z * ssc[4 * k + 2] + ssh[4 * k + 2], 0.f);
            in[4 * k + 3] = fmaxf(v.w * ssc[4 * k + 3] + ssh[4 * k + 3], 0.f);
        }
    }
    float d = g_dinv[n];
    float4* out = (float4*)(g_y + (size_t)n * HID);
#pragma unroll 1
    for (int j4 = 0; j4 < HID / 4; j4++) {
        float a0 = 0.f, a1 = 0.f, a2 = 0.f, a3 = 0.f;
#pragma unroll
        for (int k = 0; k < K; k++) {
            float xv = in[k];
            float4 w = *(const float4*)(sW + k * HID + j4 * 4);
            a0 += xv * w.x; a1 += xv * w.y; a2 += xv * w.z; a3 += xv * w.w;
        }
        out[j4] = make_float4(a0 * d, a1 * d, a2 * d, a3 * d);
    }
}

// ---------------- CSR aggregate: z = dinv*(sum_nbr y + y_self) + b ; BN stats ----------------
// 2048 blocks x 256 threads = 16384 warps; each warp handles 8 nodes.
__global__ __launch_bounds__(256) void agg_kernel(const float* __restrict__ b) {
    int warp = blockIdx.x * 8 + (threadIdx.x >> 5);
    int lane = threadIdx.x & 31;
    float bf0 = b[2 * lane], bf1 = b[2 * lane + 1];
    float s0 = 0.f, s1 = 0.f, ss0 = 0.f, ss1 = 0.f;
#pragma unroll 1
    for (int rep = 0; rep < 8; rep++) {
        int n = warp + rep * 16384;
        int rs = g_rowstart[n];
        int deg = g_degi[n];
        float2 self = *(const float2*)(g_y + (size_t)n * HID + 2 * lane);
        float a0 = self.x, a1 = self.y;
        int j = (deg > 0) ? __ldg(&g_srt[rs]) : 0;
        for (int p = 0; p < deg; p++) {
            int jn = (p + 1 < deg) ? __ldg(&g_srt[rs + p + 1]) : 0;
            float2 v = *(const float2*)(g_y + (size_t)j * HID + 2 * lane);
            a0 += v.x; a1 += v.y;
            j = jn;
        }
        float d = g_dinv[n];
        float z0 = d * a0 + bf0, z1 = d * a1 + bf1;
        *(float2*)(g_z + (size_t)n * HID + 2 * lane) = make_float2(z0, z1);
        s0 += z0; s1 += z1; ss0 += z0 * z0; ss1 += z1 * z1;
    }
    __shared__ float shs[8][64], shq[8][64];
    int w = threadIdx.x >> 5;
    shs[w][2 * lane] = s0; shs[w][2 * lane + 1] = s1;
    shq[w][2 * lane] = ss0; shq[w][2 * lane + 1] = ss1;
    __syncthreads();
    if (threadIdx.x < 64) {
        float s = 0.f, q = 0.f;
#pragma unroll
        for (int i = 0; i < 8; i++) { s += shs[i][threadIdx.x]; q += shq[i][threadIdx.x]; }
        atomicAdd(&g_bnsum[threadIdx.x], s);
        atomicAdd(&g_bnsumsq[threadIdx.x], q);
    }
}

// ---------------- BN finalize (and reset sums for next use) ----------------
__global__ void bnfin_kernel(const float* __restrict__ gamma,
                             const float* __restrict__ beta) {
    int f = threadIdx.x;
    if (f >= HID) return;
    const float inv_n = 1.0f / (float)N_NODES;
    float mu = g_bnsum[f] * inv_n;
    float var = g_bnsumsq[f] * inv_n - mu * mu;
    float rstd = rsqrtf(var + BN_EPS);
    float sc = rstd * gamma[f];
    g_scale[f] = sc;
    g_shift[f] = beta[f] - mu * sc;
    g_bnsum[f] = 0.f;
    g_bnsumsq[f] = 0.f;
}

// ---------------- pooling ----------------
__global__ void count_kernel(const int* __restrict__ batch) {
    int n = blockIdx.x * 256 + threadIdx.x;
    if (n < N_NODES) atomicAdd(&g_cnt[batch[n]], 1);
}

__global__ __launch_bounds__(1024) void prefix_kernel() {
    __shared__ int sh[N_GRAPHS];
    int t = threadIdx.x;
    int c = g_cnt[t];
    sh[t] = c;
    __syncthreads();
    for (int off = 1; off < N_GRAPHS; off <<= 1) {
        int v = (t >= off) ? sh[t - off] : 0;
        __syncthreads();
        sh[t] += v;
        __syncthreads();
    }
    g_start[t] = sh[t] - c;
}

// pooled = mean over graph nodes of relu(z*scale + shift)  (layer-2 BN applied here)
__global__ __launch_bounds__(256) void pool_kernel() {
    int idx = blockIdx.x * 256 + threadIdx.x;  // N_GRAPHS * HID
    if (idx >= N_GRAPHS * HID) return;
    int g = idx >> 6, f = idx & 63;
    int s = g_start[g], c = g_cnt[g];
    float sc = g_scale[f], sh = g_shift[f];
    float sum = 0.f;
    for (int i = 0; i < c; i++) {
        float z = g_z[(size_t)(s + i) * HID + f];
        sum += fmaxf(z * sc + sh, 0.f);
    }
    g_pooled[idx] = sum / (float)max(c, 1);
}

// ---------------- final MLP heads (one warp per graph) ----------------
__global__ __launch_bounds__(256) void mlp_kernel(
    const float* __restrict__ gf,
    const float* __restrict__ Wo1, const float* __restrict__ bo1,
    const float* __restrict__ Wo2, const float* __restrict__ bo2,
    const float* __restrict__ Wb1, const float* __restrict__ bb1,
    const float* __restrict__ Wb2, const float* __restrict__ bb2,
    float* __restrict__ out) {
    int warp = (blockIdx.x * 256 + threadIdx.x) >> 5;
    int lane = threadIdx.x & 31;
    if (warp >= N_GRAPHS) return;
    int g = warp;
    float hO = bo1[lane], hB = bb1[lane];
#pragma unroll 4
    for (int i = 0; i < HID + G_FEAT; i++) {
        float ci = (i < HID) ? g_pooled[(size_t)g * HID + i]
                             : gf[(size_t)g * G_FEAT + (i - HID)];
        hO += ci * Wo1[i * 32 + lane];
        hB += ci * Wb1[i * 32 + lane];
    }
    hO = fmaxf(hO, 0.f);
    hB = fmaxf(hB, 0.f);
    float vO = hO * Wo2[lane];
    float vB = hB * Wb2[lane];
#pragma unroll
    for (int off = 16; off; off >>= 1) {
        vO += __shfl_down_sync(0xffffffffu, vO, off);
        vB += __shfl_down_sync(0xffffffffu, vB, off);
    }
    if (lane == 0) {
        out[g] = vO + bo2[0];
        out[N_GRAPHS + g] = vB + bb2[0];
    }
}

// ---------------- launch ----------------
extern "C" void kernel_launch(void* const* d_in, const int* in_sizes, int n_in,
                              void* d_out, int out_size) {
    const float* x      = (const float*)d_in[0];
    const int*   ei     = (const int*)  d_in[1];
    const int*   batch  = (const int*)  d_in[2];
    const float* gfeat  = (const float*)d_in[3];
    const float* W1     = (const float*)d_in[4];
    const float* b1     = (const float*)d_in[5];
    const float* gamma1 = (const float*)d_in[6];
    const float* beta1  = (const float*)d_in[7];
    const float* W2     = (const float*)d_in[8];
    const float* b2     = (const float*)d_in[9];
    const float* gamma2 = (const float*)d_in[10];
    const float* beta2  = (const float*)d_in[11];
    const float* Wo1    = (const float*)d_in[12];
    const float* bo1    = (const float*)d_in[13];
    const float* Wo2    = (const float*)d_in[14];
    const float* bo2    = (const float*)d_in[15];
    const float* Wb1    = (const float*)d_in[16];
    const float* bb1    = (const float*)d_in[17];
    const float* Wb2    = (const float*)d_in[18];
    const float* bb2    = (const float*)d_in[19];
    float* out = (float*)d_out;

    const int EB = (N_EDGES + 255) / 256;   // 8192
    const int NB = (N_NODES + 255) / 256;   // 512

    zero_kernel<<<NB, 256>>>();
    deg_kernel<<<EB, 256>>>(ei);
    dinv_kernel<<<NB, 256>>>();
    scan_kernel<<<1, 1024>>>();
    bucket_kernel<<<EB, 256>>>(ei);
    count_kernel<<<NB, 256>>>(batch);
    prefix_kernel<<<1, 1024>>>();

    // ---- layer 1 ----
    xw_kernel<F_IN, false><<<N_NODES / 128, 128>>>(x, W1);
    agg_kernel<<<2048, 256>>>(b1);
    bnfin_kernel<<<1, 64>>>(gamma1, beta1);

    // ---- layer 2 (BN1+relu fused into input read) ----
    xw_kernel<HID, true><<<N_NODES / 128, 128>>>(nullptr, W2);
    agg_kernel<<<2048, 256>>>(b2);
    bnfin_kernel<<<1, 64>>>(gamma2, beta2);

    // ---- pooling (BN2+relu fused) + heads ----
    pool_kernel<<<N_GRAPHS * HID / 256, 256>>>();
    mlp_kernel<<<N_GRAPHS / 8, 256>>>(gfeat, Wo1, bo1, Wo2, bo2,
                                      Wb1, bb1, Wb2, bb2, out);
}

// round 3
// speedup vs baseline: 2.1401x; 2.1401x over previous
#include <cuda_runtime.h>
#include <cstdint>

#define N_NODES  131072
#define N_EDGES  2097152
#define F_IN     32
#define HID      64
#define G_FEAT   16
#define N_GRAPHS 1024
#define BN_EPS   1e-5f

// ---------------- device scratch ----------------
__device__ int   g_degi[N_NODES];
__device__ int   g_rowstart[N_NODES];
__device__ int   g_fill[N_NODES];
__device__ int   g_srt[N_EDGES];
__device__ int   g_blocksum[512];
__device__ int   g_blockoff[512];
__device__ float g_dinv[N_NODES];
__device__ float g_y[(size_t)N_NODES * HID];
__device__ float g_z[(size_t)N_NODES * HID];
__device__ float g_bnsum[HID];
__device__ float g_bnsumsq[HID];
__device__ float g_scale[HID];
__device__ float g_shift[HID];
__device__ int   g_cnt[N_GRAPHS];
__device__ int   g_start[N_GRAPHS];
__device__ float g_pooled[(size_t)N_GRAPHS * HID];

// ---------------- init ----------------
__global__ void zero_kernel() {
    int t = blockIdx.x * 256 + threadIdx.x;
    if (t < N_NODES) g_degi[t] = 0;
    if (t < HID) { g_bnsum[t] = 0.f; g_bnsumsq[t] = 0.f; }
    if (t < N_GRAPHS) g_cnt[t] = 0;
}

// ---------------- degree (in-degree of dst) ----------------
__global__ void deg_kernel(const int* __restrict__ ei) {
    int e = blockIdx.x * 256 + threadIdx.x;
    if (e < N_EDGES) {
        int d = __ldg(ei + N_EDGES + e);
        unsigned one = 1u;
        asm volatile("red.global.add.u32 [%0], %1;" :: "l"((unsigned*)(g_degi + d)), "r"(one) : "memory");
    }
}

// ---------------- parallel exclusive scan of degrees ----------------
// Phase A: per-block scan (512 blocks x 256 nodes)
__global__ __launch_bounds__(256) void scanA_kernel() {
    __shared__ int sh[256];
    int n = blockIdx.x * 256 + threadIdx.x;
    int d = g_degi[n];
    sh[threadIdx.x] = d;
    __syncthreads();
#pragma unroll
    for (int off = 1; off < 256; off <<= 1) {
        int v = (threadIdx.x >= off) ? sh[threadIdx.x - off] : 0;
        __syncthreads();
        sh[threadIdx.x] += v;
        __syncthreads();
    }
    g_rowstart[n] = sh[threadIdx.x] - d;      // local exclusive
    if (threadIdx.x == 255) g_blocksum[blockIdx.x] = sh[255];
}

// Phase B: scan 512 block sums (1 block)
__global__ __launch_bounds__(512) void scanB_kernel() {
    __shared__ int sh[512];
    int t = threadIdx.x;
    int v0 = g_blocksum[t];
    sh[t] = v0;
    __syncthreads();
#pragma unroll
    for (int off = 1; off < 512; off <<= 1) {
        int v = (t >= off) ? sh[t - off] : 0;
        __syncthreads();
        sh[t] += v;
        __syncthreads();
    }
    g_blockoff[t] = sh[t] - v0;               // exclusive
}

// Phase C: add offsets, init fill, compute dinv
__global__ __launch_bounds__(256) void scanC_kernel() {
    int n = blockIdx.x * 256 + threadIdx.x;
    int rs = g_rowstart[n] + g_blockoff[blockIdx.x];
    g_rowstart[n] = rs;
    g_fill[n] = rs;
    g_dinv[n] = rsqrtf((float)g_degi[n] + 1.0f);
}

// ---------------- bucket edges by dst ----------------
__global__ void bucket_kernel(const int* __restrict__ ei) {
    int e = blockIdx.x * 256 + threadIdx.x;
    if (e < N_EDGES) {
        int src = __ldg(ei + e);
        int dst = __ldg(ei + N_EDGES + e);
        int pos = atomicAdd(&g_fill[dst], 1);
        g_srt[pos] = src;
    }
}

// ---------------- y = (in @ W) * dinv  (optionally affine+relu on input) ----------------
template <int K, bool AFFINE>
__global__ __launch_bounds__(128) void xw_kernel(const float* __restrict__ xin,
                                                 const float* __restrict__ W) {
    __shared__ float sW[K * HID];
    __shared__ float ssc[HID], ssh[HID];
    for (int i = threadIdx.x; i < K * HID; i += 128) sW[i] = W[i];
    if (AFFINE && threadIdx.x < HID) {
        ssc[threadIdx.x] = g_scale[threadIdx.x];
        ssh[threadIdx.x] = g_shift[threadIdx.x];
    }
    __syncthreads();
    int n = blockIdx.x * 128 + threadIdx.x;
    float in[K];
    if (!AFFINE) {
        const float4* r = (const float4*)(xin + (size_t)n * K);
#pragma unroll
        for (int k = 0; k < K / 4; k++) {
            float4 v = __ldg(r + k);
            in[4 * k + 0] = v.x; in[4 * k + 1] = v.y;
            in[4 * k + 2] = v.z; in[4 * k + 3] = v.w;
        }
    } else {
        const float4* r = (const float4*)(g_z + (size_t)n * HID);
#pragma unroll
        for (int k = 0; k < K / 4; k++) {
            float4 v = r[k];
            in[4 * k + 0] = fmaxf(v.x * ssc[4 * k + 0] + ssh[4 * k + 0], 0.f);
            in[4 * k + 1] = fmaxf(v.y * ssc[4 * k + 1] + ssh[4 * k + 1], 0.f);
            in[4 * k + 2] = fmaxf(v.z * ssc[4 * k + 2] + ssh[4 * k + 2], 0.f);
            in[4 * k + 3] = fmaxf(v.w * ssc[4 * k + 3] + ssh[4 * k + 3], 0.f);
        }
    }
    float d = g_dinv[n];
    float4* out = (float4*)(g_y + (size_t)n * HID);
#pragma unroll 1
    for (int j4 = 0; j4 < HID / 4; j4++) {
        float a0 = 0.f, a1 = 0.f, a2 = 0.f, a3 = 0.f;
#pragma unroll
        for (int k = 0; k < K; k++) {
            float xv = in[k];
            float4 w = *(const float4*)(sW + k * HID + j4 * 4);
            a0 += xv * w.x; a1 += xv * w.y; a2 += xv * w.z; a3 += xv * w.w;
        }
        out[j4] = make_float4(a0 * d, a1 * d, a2 * d, a3 * d);
    }
}

// ---------------- CSR aggregate: z = dinv*(sum_nbr y + y_self) + b ; BN stats ----------------
// 2048 blocks x 256 threads = 16384 warps; each warp handles 8 nodes.
__global__ __launch_bounds__(256) void agg_kernel(const float* __restrict__ b) {
    int warp = blockIdx.x * 8 + (threadIdx.x >> 5);
    int lane = threadIdx.x & 31;
    float bf0 = b[2 * lane], bf1 = b[2 * lane + 1];
    float s0 = 0.f, s1 = 0.f, ss0 = 0.f, ss1 = 0.f;
#pragma unroll 1
    for (int rep = 0; rep < 8; rep++) {
        int n = warp + rep * 16384;
        int rs = g_rowstart[n];
        int deg = g_degi[n];
        float2 self = *(const float2*)(g_y + (size_t)n * HID + 2 * lane);
        float a0 = self.x, a1 = self.y;
        int j = (deg > 0) ? __ldg(&g_srt[rs]) : 0;
        for (int p = 0; p < deg; p++) {
            int jn = (p + 1 < deg) ? __ldg(&g_srt[rs + p + 1]) : 0;
            float2 v = *(const float2*)(g_y + (size_t)j * HID + 2 * lane);
            a0 += v.x; a1 += v.y;
            j = jn;
        }
        float d = g_dinv[n];
        float z0 = d * a0 + bf0, z1 = d * a1 + bf1;
        *(float2*)(g_z + (size_t)n * HID + 2 * lane) = make_float2(z0, z1);
        s0 += z0; s1 += z1; ss0 += z0 * z0; ss1 += z1 * z1;
    }
    __shared__ float shs[8][64], shq[8][64];
    int w = threadIdx.x >> 5;
    shs[w][2 * lane] = s0; shs[w][2 * lane + 1] = s1;
    shq[w][2 * lane] = ss0; shq[w][2 * lane + 1] = ss1;
    __syncthreads();
    if (threadIdx.x < 64) {
        float s = 0.f, q = 0.f;
#pragma unroll
        for (int i = 0; i < 8; i++) { s += shs[i][threadIdx.x]; q += shq[i][threadIdx.x]; }
        atomicAdd(&g_bnsum[threadIdx.x], s);
        atomicAdd(&g_bnsumsq[threadIdx.x], q);
    }
}

// ---------------- BN finalize (and reset sums for next use) ----------------
__global__ void bnfin_kernel(const float* __restrict__ gamma,
                             const float* __restrict__ beta) {
    int f = threadIdx.x;
    if (f >= HID) return;
    const float inv_n = 1.0f / (float)N_NODES;
    float mu = g_bnsum[f] * inv_n;
    float var = g_bnsumsq[f] * inv_n - mu * mu;
    float rstd = rsqrtf(var + BN_EPS);
    float sc = rstd * gamma[f];
    g_scale[f] = sc;
    g_shift[f] = beta[f] - mu * sc;
    g_bnsum[f] = 0.f;
    g_bnsumsq[f] = 0.f;
}

// ---------------- pooling ----------------
__global__ void count_kernel(const int* __restrict__ batch) {
    int n = blockIdx.x * 256 + threadIdx.x;
    if (n < N_NODES) atomicAdd(&g_cnt[batch[n]], 1);
}

__global__ __launch_bounds__(1024) void prefix_kernel() {
    __shared__ int sh[N_GRAPHS];
    int t = threadIdx.x;
    int c = g_cnt[t];
    sh[t] = c;
    __syncthreads();
    for (int off = 1; off < N_GRAPHS; off <<= 1) {
        int v = (t >= off) ? sh[t - off] : 0;
        __syncthreads();
        sh[t] += v;
        __syncthreads();
    }
    g_start[t] = sh[t] - c;
}

// pooled = mean over graph nodes of relu(z*scale + shift)  (layer-2 BN applied here)
__global__ __launch_bounds__(256) void pool_kernel() {
    int idx = blockIdx.x * 256 + threadIdx.x;  // N_GRAPHS * HID
    if (idx >= N_GRAPHS * HID) return;
    int g = idx >> 6, f = idx & 63;
    int s = g_start[g], c = g_cnt[g];
    float sc = g_scale[f], sh = g_shift[f];
    float sum = 0.f;
    for (int i = 0; i < c; i++) {
        float z = g_z[(size_t)(s + i) * HID + f];
        sum += fmaxf(z * sc + sh, 0.f);
    }
    g_pooled[idx] = sum / (float)max(c, 1);
}

// ---------------- final MLP heads (one warp per graph) ----------------
__global__ __launch_bounds__(256) void mlp_kernel(
    const float* __restrict__ gf,
    const float* __restrict__ Wo1, const float* __restrict__ bo1,
    const float* __restrict__ Wo2, const float* __restrict__ bo2,
    const float* __restrict__ Wb1, const float* __restrict__ bb1,
    const float* __restrict__ Wb2, const float* __restrict__ bb2,
    float* __restrict__ out) {
    int warp = (blockIdx.x * 256 + threadIdx.x) >> 5;
    int lane = threadIdx.x & 31;
    if (warp >= N_GRAPHS) return;
    int g = warp;
    float hO = bo1[lane], hB = bb1[lane];
#pragma unroll 4
    for (int i = 0; i < HID + G_FEAT; i++) {
        float ci = (i < HID) ? g_pooled[(size_t)g * HID + i]
                             : gf[(size_t)g * G_FEAT + (i - HID)];
        hO += ci * Wo1[i * 32 + lane];
        hB += ci * Wb1[i * 32 + lane];
    }
    hO = fmaxf(hO, 0.f);
    hB = fmaxf(hB, 0.f);
    float vO = hO * Wo2[lane];
    float vB = hB * Wb2[lane];
#pragma unroll
    for (int off = 16; off; off >>= 1) {
        vO += __shfl_down_sync(0xffffffffu, vO, off);
        vB += __shfl_down_sync(0xffffffffu, vB, off);
    }
    if (lane == 0) {
        out[g] = vO + bo2[0];
        out[N_GRAPHS + g] = vB + bb2[0];
    }
}

// ---------------- launch ----------------
extern "C" void kernel_launch(void* const* d_in, const int* in_sizes, int n_in,
                              void* d_out, int out_size) {
    const float* x      = (const float*)d_in[0];
    const int*   ei     = (const int*)  d_in[1];
    const int*   batch  = (const int*)  d_in[2];
    const float* gfeat  = (const float*)d_in[3];
    const float* W1     = (const float*)d_in[4];
    const float* b1     = (const float*)d_in[5];
    const float* gamma1 = (const float*)d_in[6];
    const float* beta1  = (const float*)d_in[7];
    const float* W2     = (const float*)d_in[8];
    const float* b2     = (const float*)d_in[9];
    const float* gamma2 = (const float*)d_in[10];
    const float* beta2  = (const float*)d_in[11];
    const float* Wo1    = (const float*)d_in[12];
    const float* bo1    = (const float*)d_in[13];
    const float* Wo2    = (const float*)d_in[14];
    const float* bo2    = (const float*)d_in[15];
    const float* Wb1    = (const float*)d_in[16];
    const float* bb1    = (const float*)d_in[17];
    const float* Wb2    = (const float*)d_in[18];
    const float* bb2    = (const float*)d_in[19];
    float* out = (float*)d_out;

    const int EB = (N_EDGES + 255) / 256;   // 8192
    const int NB = (N_NODES + 255) / 256;   // 512

    zero_kernel<<<NB, 256>>>();
    deg_kernel<<<EB, 256>>>(ei);
    scanA_kernel<<<512, 256>>>();
    scanB_kernel<<<1, 512>>>();
    scanC_kernel<<<512, 256>>>();
    bucket_kernel<<<EB, 256>>>(ei);
    count_kernel<<<NB, 256>>>(batch);
    prefix_kernel<<<1, 1024>>>();

    // ---- layer 1 ----
    xw_kernel<F_IN, false><<<N_NODES / 128, 128>>>(x, W1);
    agg_kernel<<<2048, 256>>>(b1);
    bnfin_kernel<<<1, 64>>>(gamma1, beta1);

    // ---- layer 2 (BN1+relu fused into input read) ----
    xw_kernel<HID, true><<<N_NODES / 128, 128>>>(nullptr, W2);
    agg_kernel<<<2048, 256>>>(b2);
    bnfin_kernel<<<1, 64>>>(gamma2, beta2);

    // ---- pooling (BN2+relu fused) + heads ----
    pool_kernel<<<N_GRAPHS * HID / 256, 256>>>();
    mlp_kernel<<<N_GRAPHS / 8, 256>>>(gfeat, Wo1, bo1, Wo2, bo2,
                                      Wb1, bb1, Wb2, bb2, out);
}

// round 4
// speedup vs baseline: 2.2892x; 1.0697x over previous
#include <cuda_runtime.h>
#include <cuda_fp16.h>
#include <cstdint>

#define N_NODES  131072
#define N_EDGES  2097152
#define F_IN     32
#define HID      64
#define G_FEAT   16
#define N_GRAPHS 1024
#define BN_EPS   1e-5f

// ---------------- device scratch ----------------
__device__ int   g_degi[N_NODES];
__device__ int   g_rowstart[N_NODES];
__device__ int   g_fill[N_NODES];
__device__ int   g_srt[N_EDGES];
__device__ int   g_blocksum[512];
__device__ int   g_blockoff[512];
__device__ float g_dinv[N_NODES];
__device__ __align__(16) __half2 g_yh[(size_t)N_NODES * 32];
__device__ __align__(16) __half2 g_zh[(size_t)N_NODES * 32];
__device__ float g_bnsum[HID];
__device__ float g_bnsumsq[HID];
__device__ float g_scale[HID];
__device__ float g_shift[HID];
__device__ int   g_cnt[N_GRAPHS];
__device__ int   g_start[N_GRAPHS];
__device__ float g_pooled[(size_t)N_GRAPHS * HID];

__device__ __forceinline__ unsigned long long ffma2(unsigned long long a,
                                                    unsigned long long b,
                                                    unsigned long long c) {
    unsigned long long d;
    asm("fma.rn.f32x2 %0, %1, %2, %3;" : "=l"(d) : "l"(a), "l"(b), "l"(c));
    return d;
}

// ---------------- init ----------------
__global__ void zero_kernel() {
    int t = blockIdx.x * 256 + threadIdx.x;
    if (t < N_NODES) g_degi[t] = 0;
    if (t < HID) { g_bnsum[t] = 0.f; g_bnsumsq[t] = 0.f; }
    if (t < N_GRAPHS) g_cnt[t] = 0;
}

// ---------------- degree + graph counts ----------------
__global__ void deg_kernel(const int* __restrict__ ei, const int* __restrict__ batch) {
    int t = blockIdx.x * 256 + threadIdx.x;
    if (t < N_EDGES) {
        int d = __ldg(ei + N_EDGES + t);
        unsigned one = 1u;
        asm volatile("red.global.add.u32 [%0], %1;" :: "l"((unsigned*)(g_degi + d)), "r"(one) : "memory");
    }
    if (t < N_NODES) atomicAdd(&g_cnt[__ldg(batch + t)], 1);
}

// ---------------- parallel exclusive scan of degrees ----------------
__global__ __launch_bounds__(256) void scanA_kernel() {
    __shared__ int sh[256];
    int n = blockIdx.x * 256 + threadIdx.x;
    int d = g_degi[n];
    sh[threadIdx.x] = d;
    __syncthreads();
#pragma unroll
    for (int off = 1; off < 256; off <<= 1) {
        int v = (threadIdx.x >= off) ? sh[threadIdx.x - off] : 0;
        __syncthreads();
        sh[threadIdx.x] += v;
        __syncthreads();
    }
    g_rowstart[n] = sh[threadIdx.x] - d;
    if (threadIdx.x == 255) g_blocksum[blockIdx.x] = sh[255];
}

// scan 512 block sums + scan graph counts (prefix) in one block
__global__ __launch_bounds__(1024) void scanB_kernel() {
    __shared__ int sb[512];
    __shared__ int sc[1024];
    int t = threadIdx.x;
    int v0 = 0;
    if (t < 512) { v0 = g_blocksum[t]; sb[t] = v0; }
    int c = g_cnt[t];
    sc[t] = c;
    __syncthreads();
#pragma unroll
    for (int off = 1; off < 1024; off <<= 1) {
        int vb = (t < 512 && t >= off) ? sb[t - off] : 0;
        int vc = (t >= off) ? sc[t - off] : 0;
        __syncthreads();
        if (t < 512) sb[t] += vb;
        sc[t] += vc;
        __syncthreads();
    }
    if (t < 512) g_blockoff[t] = sb[t] - v0;
    g_start[t] = sc[t] - c;
}

__global__ __launch_bounds__(256) void scanC_kernel() {
    int n = blockIdx.x * 256 + threadIdx.x;
    int rs = g_rowstart[n] + g_blockoff[blockIdx.x];
    g_rowstart[n] = rs;
    g_fill[n] = rs;
    g_dinv[n] = rsqrtf((float)g_degi[n] + 1.0f);
}

// ---------------- bucket edges by dst ----------------
__global__ void bucket_kernel(const int* __restrict__ ei) {
    int e = blockIdx.x * 256 + threadIdx.x;
    if (e < N_EDGES) {
        int src = __ldg(ei + e);
        int dst = __ldg(ei + N_EDGES + e);
        int pos = atomicAdd(&g_fill[dst], 1);
        g_srt[pos] = src;
    }
}

// ---------------- y = (in @ W) * dinv  (fp16 out, optional BN-affine+relu input) ----------------
template <int K, bool AFFINE>
__global__ __launch_bounds__(128) void xw_kernel(const float* __restrict__ xin,
                                                 const float* __restrict__ W) {
    __shared__ __align__(16) float sW[K * HID];
    __shared__ float ssc[HID], ssh[HID];
    __shared__ __half2 sOut[128][33];   // pad 33 -> conflict-free 4B access
    int tid = threadIdx.x;
    for (int i = tid; i < K * HID; i += 128) sW[i] = W[i];
    if (AFFINE && tid < HID) { ssc[tid] = g_scale[tid]; ssh[tid] = g_shift[tid]; }
    __syncthreads();
    int n = blockIdx.x * 128 + tid;
    float in[K];
    if (!AFFINE) {
        const float4* r = (const float4*)(xin + (size_t)n * K);
#pragma unroll
        for (int q = 0; q < K / 4; q++) {
            float4 v = __ldg(r + q);
            in[4 * q + 0] = v.x; in[4 * q + 1] = v.y;
            in[4 * q + 2] = v.z; in[4 * q + 3] = v.w;
        }
    } else {
        const uint4* r = (const uint4*)(g_zh + (size_t)n * 32);
#pragma unroll
        for (int q = 0; q < 8; q++) {
            uint4 u = __ldg(r + q);
            unsigned uu[4] = {u.x, u.y, u.z, u.w};
#pragma unroll
            for (int m = 0; m < 4; m++) {
                float2 f = __half22float2(*(__half2*)&uu[m]);
                int fbase = 8 * q + 2 * m;
                in[fbase + 0] = fmaxf(f.x * ssc[fbase + 0] + ssh[fbase + 0], 0.f);
                in[fbase + 1] = fmaxf(f.y * ssc[fbase + 1] + ssh[fbase + 1], 0.f);
            }
        }
    }
    float d = g_dinv[n];
#pragma unroll 1
    for (int jb = 0; jb < 4; jb++) {    // 16 feats (8 pairs) per block
        unsigned long long acc[8];
#pragma unroll
        for (int m = 0; m < 8; m++) acc[m] = 0ull;
#pragma unroll 4
        for (int k = 0; k < K; k++) {
            unsigned long long xp;
            asm("mov.b64 %0, {%1, %1};" : "=l"(xp) : "r"(__float_as_uint(in[k])));
            const ulonglong2* wp = (const ulonglong2*)(sW + k * HID + jb * 16);
            ulonglong2 w01 = wp[0], w23 = wp[1], w45 = wp[2], w67 = wp[3];
            acc[0] = ffma2(xp, w01.x, acc[0]);
            acc[1] = ffma2(xp, w01.y, acc[1]);
            acc[2] = ffma2(xp, w23.x, acc[2]);
            acc[3] = ffma2(xp, w23.y, acc[3]);
            acc[4] = ffma2(xp, w45.x, acc[4]);
            acc[5] = ffma2(xp, w45.y, acc[5]);
            acc[6] = ffma2(xp, w67.x, acc[6]);
            acc[7] = ffma2(xp, w67.y, acc[7]);
        }
#pragma unroll
        for (int m = 0; m < 8; m++) {
            float lo, hi;
            asm("mov.b64 {%0, %1}, %2;" : "=f"(lo), "=f"(hi) : "l"(acc[m]));
            sOut[tid][jb * 8 + m] = __floats2half2_rn(lo * d, hi * d);
        }
    }
    __syncthreads();
    // cooperative coalesced write: 128 nodes x 32 half2 (4B units)
    unsigned* dst = (unsigned*)(g_yh + (size_t)blockIdx.x * 128 * 32);
    const unsigned* srcBase = (const unsigned*)sOut;
#pragma unroll
    for (int i = tid; i < 4096; i += 128) {
        int node = i >> 5, c = i & 31;
        dst[i] = srcBase[node * 33 + c];
    }
}

// ---------------- CSR aggregate (coalesced index + unrolled gather) ----------------
// 2048 blocks x 256 threads; warp handles 8 contiguous nodes; lane covers feats 2l,2l+1.
__global__ __launch_bounds__(256) void agg_kernel(const float* __restrict__ b) {
    int warp = blockIdx.x * 8 + (threadIdx.x >> 5);
    int lane = threadIdx.x & 31;
    float bf0 = __ldg(b + 2 * lane), bf1 = __ldg(b + 2 * lane + 1);
    float s0 = 0.f, s1 = 0.f, q0 = 0.f, q1 = 0.f;
    int nbase = warp * 8;
#pragma unroll 1
    for (int rep = 0; rep < 8; rep++) {
        int n = nbase + rep;
        int rs = __ldg(&g_rowstart[n]);
        int deg = __ldg(&g_degi[n]);
        float2 a = __half22float2(g_yh[(size_t)n * 32 + lane]);
        for (int base = 0; base < deg; base += 32) {
            int rem = deg - base;
            int cnt = rem < 32 ? rem : 32;
            int idx = (lane < cnt) ? __ldg(&g_srt[rs + base + lane]) : 0;
            int p = 0;
            for (; p + 4 <= cnt; p += 4) {
                int j0 = __shfl_sync(0xffffffffu, idx, p);
                int j1 = __shfl_sync(0xffffffffu, idx, p + 1);
                int j2 = __shfl_sync(0xffffffffu, idx, p + 2);
                int j3 = __shfl_sync(0xffffffffu, idx, p + 3);
                __half2 h0 = g_yh[(size_t)j0 * 32 + lane];
                __half2 h1 = g_yh[(size_t)j1 * 32 + lane];
                __half2 h2 = g_yh[(size_t)j2 * 32 + lane];
                __half2 h3 = g_yh[(size_t)j3 * 32 + lane];
                float2 f0 = __half22float2(h0), f1 = __half22float2(h1);
                float2 f2 = __half22float2(h2), f3 = __half22float2(h3);
                a.x += (f0.x + f1.x) + (f2.x + f3.x);
                a.y += (f0.y + f1.y) + (f2.y + f3.y);
            }
            for (; p < cnt; p++) {
                int j = __shfl_sync(0xffffffffu, idx, p);
                float2 f = __half22float2(g_yh[(size_t)j * 32 + lane]);
                a.x += f.x; a.y += f.y;
            }
        }
        float d = __ldg(&g_dinv[n]);
        float z0 = d * a.x + bf0, z1 = d * a.y + bf1;
        g_zh[(size_t)n * 32 + lane] = __floats2half2_rn(z0, z1);
        s0 += z0; s1 += z1; q0 += z0 * z0; q1 += z1 * z1;
    }
    __shared__ float shs[8][64], shq[8][64];
    int w = threadIdx.x >> 5;
    shs[w][2 * lane] = s0; shs[w][2 * lane + 1] = s1;
    shq[w][2 * lane] = q0; shq[w][2 * lane + 1] = q1;
    __syncthreads();
    if (threadIdx.x < 64) {
        float s = 0.f, q = 0.f;
#pragma unroll
        for (int i = 0; i < 8; i++) { s += shs[i][threadIdx.x]; q += shq[i][threadIdx.x]; }
        atomicAdd(&g_bnsum[threadIdx.x], s);
        atomicAdd(&g_bnsumsq[threadIdx.x], q);
    }
}

// ---------------- BN finalize (and reset sums) ----------------
__global__ void bnfin_kernel(const float* __restrict__ gamma,
                             const float* __restrict__ beta) {
    int f = threadIdx.x;
    if (f >= HID) return;
    const float inv_n = 1.0f / (float)N_NODES;
    float mu = g_bnsum[f] * inv_n;
    float var = g_bnsumsq[f] * inv_n - mu * mu;
    float rstd = rsqrtf(var + BN_EPS);
    float sc = rstd * gamma[f];
    g_scale[f] = sc;
    g_shift[f] = beta[f] - mu * sc;
    g_bnsum[f] = 0.f;
    g_bnsumsq[f] = 0.f;
}

// ---------------- pooling: mean over graph of relu(z*scale+shift) ----------------
__global__ __launch_bounds__(256) void pool_kernel() {
    int t = blockIdx.x * 256 + threadIdx.x;   // 32768 threads
    int g = t >> 5, j2 = t & 31;
    int s = g_start[g], c = g_cnt[g];
    float sc0 = g_scale[2 * j2], sc1 = g_scale[2 * j2 + 1];
    float sh0 = g_shift[2 * j2], sh1 = g_shift[2 * j2 + 1];
    float s0 = 0.f, s1 = 0.f;
    int i = 0;
    for (; i + 4 <= c; i += 4) {
        float2 f0 = __half22float2(g_zh[(size_t)(s + i + 0) * 32 + j2]);
        float2 f1 = __half22float2(g_zh[(size_t)(s + i + 1) * 32 + j2]);
        float2 f2 = __half22float2(g_zh[(size_t)(s + i + 2) * 32 + j2]);
        float2 f3 = __half22float2(g_zh[(size_t)(s + i + 3) * 32 + j2]);
        s0 += fmaxf(f0.x * sc0 + sh0, 0.f) + fmaxf(f1.x * sc0 + sh0, 0.f)
            + fmaxf(f2.x * sc0 + sh0, 0.f) + fmaxf(f3.x * sc0 + sh0, 0.f);
        s1 += fmaxf(f0.y * sc1 + sh1, 0.f) + fmaxf(f1.y * sc1 + sh1, 0.f)
            + fmaxf(f2.y * sc1 + sh1, 0.f) + fmaxf(f3.y * sc1 + sh1, 0.f);
    }
    for (; i < c; i++) {
        float2 f = __half22float2(g_zh[(size_t)(s + i) * 32 + j2]);
        s0 += fmaxf(f.x * sc0 + sh0, 0.f);
        s1 += fmaxf(f.y * sc1 + sh1, 0.f);
    }
    float inv = 1.0f / (float)max(c, 1);
    *(float2*)(g_pooled + (size_t)g * HID + 2 * j2) = make_float2(s0 * inv, s1 * inv);
}

// ---------------- final MLP heads (one warp per graph) ----------------
__global__ __launch_bounds__(256) void mlp_kernel(
    const float* __restrict__ gf,
    const float* __restrict__ Wo1, const float* __restrict__ bo1,
    const float* __restrict__ Wo2, const float* __restrict__ bo2,
    const float* __restrict__ Wb1, const float* __restrict__ bb1,
    const float* __restrict__ Wb2, const float* __restrict__ bb2,
    float* __restrict__ out) {
    int warp = (blockIdx.x * 256 + threadIdx.x) >> 5;
    int lane = threadIdx.x & 31;
    if (warp >= N_GRAPHS) return;
    int g = warp;
    float hO = bo1[lane], hB = bb1[lane];
#pragma unroll 4
    for (int i = 0; i < HID + G_FEAT; i++) {
        float ci = (i < HID) ? g_pooled[(size_t)g * HID + i]
                             : gf[(size_t)g * G_FEAT + (i - HID)];
        hO += ci * Wo1[i * 32 + lane];
        hB += ci * Wb1[i * 32 + lane];
    }
    hO = fmaxf(hO, 0.f);
    hB = fmaxf(hB, 0.f);
    float vO = hO * Wo2[lane];
    float vB = hB * Wb2[lane];
#pragma unroll
    for (int off = 16; off; off >>= 1) {
        vO += __shfl_down_sync(0xffffffffu, vO, off);
        vB += __shfl_down_sync(0xffffffffu, vB, off);
    }
    if (lane == 0) {
        out[g] = vO + bo2[0];
        out[N_GRAPHS + g] = vB + bb2[0];
    }
}

// ---------------- launch ----------------
extern "C" void kernel_launch(void* const* d_in, const int* in_sizes, int n_in,
                              void* d_out, int out_size) {
    const float* x      = (const float*)d_in[0];
    const int*   ei     = (const int*)  d_in[1];
    const int*   batch  = (const int*)  d_in[2];
    const float* gfeat  = (const float*)d_in[3];
    const float* W1     = (const float*)d_in[4];
    const float* b1     = (const float*)d_in[5];
    const float* gamma1 = (const float*)d_in[6];
    const float* beta1  = (const float*)d_in[7];
    const float* W2     = (const float*)d_in[8];
    const float* b2     = (const float*)d_in[9];
    const float* gamma2 = (const float*)d_in[10];
    const float* beta2  = (const float*)d_in[11];
    const float* Wo1    = (const float*)d_in[12];
    const float* bo1    = (const float*)d_in[13];
    const float* Wo2    = (const float*)d_in[14];
    const float* bo2    = (const float*)d_in[15];
    const float* Wb1    = (const float*)d_in[16];
    const float* bb1    = (const float*)d_in[17];
    const float* Wb2    = (const float*)d_in[18];
    const float* bb2    = (const float*)d_in[19];
    float* out = (float*)d_out;

    const int EB = (N_EDGES + 255) / 256;   // 8192
    const int NB = (N_NODES + 255) / 256;   // 512

    zero_kernel<<<NB, 256>>>();
    deg_kernel<<<EB, 256>>>(ei, batch);
    scanA_kernel<<<512, 256>>>();
    scanB_kernel<<<1, 1024>>>();
    scanC_kernel<<<512, 256>>>();
    bucket_kernel<<<EB, 256>>>(ei);

    // ---- layer 1 ----
    xw_kernel<F_IN, false><<<N_NODES / 128, 128>>>(x, W1);
    agg_kernel<<<2048, 256>>>(b1);
    bnfin_kernel<<<1, 64>>>(gamma1, beta1);

    // ---- layer 2 (BN1+relu fused into input read) ----
    xw_kernel<HID, true><<<N_NODES / 128, 128>>>(nullptr, W2);
    agg_kernel<<<2048, 256>>>(b2);
    bnfin_kernel<<<1, 64>>>(gamma2, beta2);

    // ---- pooling (BN2+relu fused) + heads ----
    pool_kernel<<<128, 256>>>();
    mlp_kernel<<<N_GRAPHS / 8, 256>>>(gfeat, Wo1, bo1, Wo2, bo2,
                                      Wb1, bb1, Wb2, bb2, out);
}

// round 6
// speedup vs baseline: 2.4945x; 1.0897x over previous
#include <cuda_runtime.h>
#include <cuda_fp16.h>
#include <cstdint>

#define N_NODES  131072
#define N_EDGES  2097152
#define F_IN     32
#define HID      64
#define G_FEAT   16
#define N_GRAPHS 1024
#define BN_EPS   1e-5f

// ---------------- device scratch ----------------
__device__ int   g_degi[N_NODES];
__device__ int   g_rowstart[N_NODES];
__device__ int   g_fill[N_NODES];
__device__ int   g_srt[N_EDGES];
__device__ int   g_blocksum[512];
__device__ int   g_blockoff[512];
__device__ float g_dinv[N_NODES];
__device__ __align__(16) __half2 g_y1[(size_t)N_NODES * 16];  // dinv*x        (32 feats)
__device__ __align__(16) __half2 g_a1[(size_t)N_NODES * 16];  // dinv*agg(y1)  (32 feats)
__device__ __align__(16) __half2 g_z1[(size_t)N_NODES * 32];  // a1@W1+b1      (64 feats)
__device__ __align__(16) __half2 g_y2[(size_t)N_NODES * 32];  // dinv*relu(bn(z1))
__device__ __align__(16) __half2 g_a2[(size_t)N_NODES * 32];  // dinv*agg(y2)
__device__ __align__(16) __half2 g_z2[(size_t)N_NODES * 32];  // a2@W2+b2
__device__ float g_s1[HID], g_q1[HID], g_s2[HID], g_q2[HID];
__device__ int   g_start[N_GRAPHS + 1];
__device__ float g_pooled[(size_t)N_GRAPHS * HID];

__device__ __forceinline__ unsigned long long ffma2(unsigned long long a,
                                                    unsigned long long b,
                                                    unsigned long long c) {
    unsigned long long d;
    asm("fma.rn.f32x2 %0, %1, %2, %3;" : "=l"(d) : "l"(a), "l"(b), "l"(c));
    return d;
}
__device__ __forceinline__ void redf(float* p, float v) {
    asm volatile("red.global.add.f32 [%0], %1;" :: "l"(p), "f"(v) : "memory");
}

// ---------------- init: zero deg + bn sums, graph starts via sorted-batch boundaries ----
__global__ void zero_kernel(const int* __restrict__ batch) {
    int t = blockIdx.x * 256 + threadIdx.x;
    if (t < N_NODES) {
        g_degi[t] = 0;
        int b = __ldg(batch + t);
        int prev = (t == 0) ? -1 : __ldg(batch + t - 1);
        for (int g = prev + 1; g <= b; g++) g_start[g] = t;
        if (t == N_NODES - 1)
            for (int g = b + 1; g <= N_GRAPHS; g++) g_start[g] = N_NODES;
    }
    if (t < HID) { g_s1[t] = 0.f; g_q1[t] = 0.f; g_s2[t] = 0.f; g_q2[t] = 0.f; }
}

// ---------------- degree (vectorized) ----------------
__global__ void deg_kernel(const int* __restrict__ ei) {
    int e4 = blockIdx.x * 256 + threadIdx.x;      // N_EDGES/4 threads
    int4 d = __ldg((const int4*)(ei + N_EDGES) + e4);
    unsigned one = 1u;
    asm volatile("red.global.add.u32 [%0], %1;" :: "l"((unsigned*)(g_degi + d.x)), "r"(one) : "memory");
    asm volatile("red.global.add.u32 [%0], %1;" :: "l"((unsigned*)(g_degi + d.y)), "r"(one) : "memory");
    asm volatile("red.global.add.u32 [%0], %1;" :: "l"((unsigned*)(g_degi + d.z)), "r"(one) : "memory");
    asm volatile("red.global.add.u32 [%0], %1;" :: "l"((unsigned*)(g_degi + d.w)), "r"(one) : "memory");
}

// ---------------- 3-phase scan ----------------
__global__ __launch_bounds__(256) void scanA_kernel() {
    __shared__ int sh[256];
    int n = blockIdx.x * 256 + threadIdx.x;
    int d = g_degi[n];
    sh[threadIdx.x] = d;
    __syncthreads();
#pragma unroll
    for (int off = 1; off < 256; off <<= 1) {
        int v = (threadIdx.x >= off) ? sh[threadIdx.x - off] : 0;
        __syncthreads();
        sh[threadIdx.x] += v;
        __syncthreads();
    }
    g_rowstart[n] = sh[threadIdx.x] - d;
    if (threadIdx.x == 255) g_blocksum[blockIdx.x] = sh[255];
}

__global__ __launch_bounds__(512) void scanB_kernel() {
    __shared__ int sh[512];
    int t = threadIdx.x;
    int v0 = g_blocksum[t];
    sh[t] = v0;
    __syncthreads();
#pragma unroll
    for (int off = 1; off < 512; off <<= 1) {
        int v = (t >= off) ? sh[t - off] : 0;
        __syncthreads();
        sh[t] += v;
        __syncthreads();
    }
    g_blockoff[t] = sh[t] - v0;
}

// scanC: fixup + fill + dinv + y1 = fp16(dinv * x)
__global__ __launch_bounds__(256) void scanC_kernel(const float* __restrict__ x) {
    int n = blockIdx.x * 256 + threadIdx.x;
    int rs = g_rowstart[n] + g_blockoff[blockIdx.x];
    g_rowstart[n] = rs;
    g_fill[n] = rs;
    float d = rsqrtf((float)g_degi[n] + 1.0f);
    g_dinv[n] = d;
    const float4* xr = (const float4*)(x + (size_t)n * F_IN);
    uint4* yw = (uint4*)(g_y1 + (size_t)n * 16);
#pragma unroll
    for (int q = 0; q < 2; q++) {
        float4 v0 = __ldg(xr + 4 * q + 0);
        float4 v1 = __ldg(xr + 4 * q + 1);
        float4 v2 = __ldg(xr + 4 * q + 2);
        float4 v3 = __ldg(xr + 4 * q + 3);
        __half2 h0 = __floats2half2_rn(v0.x * d, v0.y * d);
        __half2 h1 = __floats2half2_rn(v0.z * d, v0.w * d);
        __half2 h2 = __floats2half2_rn(v1.x * d, v1.y * d);
        __half2 h3 = __floats2half2_rn(v1.z * d, v1.w * d);
        __half2 h4 = __floats2half2_rn(v2.x * d, v2.y * d);
        __half2 h5 = __floats2half2_rn(v2.z * d, v2.w * d);
        __half2 h6 = __floats2half2_rn(v3.x * d, v3.y * d);
        __half2 h7 = __floats2half2_rn(v3.z * d, v3.w * d);
        uint4 w0, w1;
        w0.x = *(unsigned*)&h0; w0.y = *(unsigned*)&h1;
        w0.z = *(unsigned*)&h2; w0.w = *(unsigned*)&h3;
        w1.x = *(unsigned*)&h4; w1.y = *(unsigned*)&h5;
        w1.z = *(unsigned*)&h6; w1.w = *(unsigned*)&h7;
        yw[2 * q + 0] = w0;
        yw[2 * q + 1] = w1;
    }
}

// ---------------- bucket edges by dst (vectorized) ----------------
__global__ void bucket_kernel(const int* __restrict__ ei) {
    int e4 = blockIdx.x * 256 + threadIdx.x;
    int4 s = __ldg((const int4*)ei + e4);
    int4 d = __ldg((const int4*)(ei + N_EDGES) + e4);
    g_srt[atomicAdd(&g_fill[d.x], 1)] = s.x;
    g_srt[atomicAdd(&g_fill[d.y], 1)] = s.y;
    g_srt[atomicAdd(&g_fill[d.z], 1)] = s.z;
    g_srt[atomicAdd(&g_fill[d.w], 1)] = s.w;
}

// ---------------- CSR aggregate, 32-feat version (layer 1) ----------------
// lane&15 covers half2 feat pair; lane>=16 handles odd neighbor of each pair.
__global__ __launch_bounds__(256) void agg1_kernel() {
    int warp = blockIdx.x * 8 + (threadIdx.x >> 5);
    int lane = threadIdx.x & 31;
    int l = lane & 15;
    int half = lane >> 4;
#pragma unroll 1
    for (int rep = 0; rep < 8; rep++) {
        int n = warp * 8 + rep;
        int rs = __ldg(&g_rowstart[n]);
        int deg = __ldg(&g_degi[n]);
        float ax = 0.f, ay = 0.f;
        for (int base = 0; base < deg; base += 32) {
            int rem = deg - base;
            int cnt = rem < 32 ? rem : 32;
            int idx = (lane < cnt) ? __ldg(&g_srt[rs + base + lane]) : 0;
            int p = 0;
            for (; p + 8 <= cnt; p += 8) {
                int j0 = __shfl_sync(0xffffffffu, idx, p + 0 + half);
                int j1 = __shfl_sync(0xffffffffu, idx, p + 2 + half);
                int j2 = __shfl_sync(0xffffffffu, idx, p + 4 + half);
                int j3 = __shfl_sync(0xffffffffu, idx, p + 6 + half);
                float2 f0 = __half22float2(g_y1[(size_t)j0 * 16 + l]);
                float2 f1 = __half22float2(g_y1[(size_t)j1 * 16 + l]);
                float2 f2 = __half22float2(g_y1[(size_t)j2 * 16 + l]);
                float2 f3 = __half22float2(g_y1[(size_t)j3 * 16 + l]);
                ax += (f0.x + f1.x) + (f2.x + f3.x);
                ay += (f0.y + f1.y) + (f2.y + f3.y);
            }
            for (; p < cnt; p += 2) {
                int sel = p + half;
                int j = __shfl_sync(0xffffffffu, idx, sel & 31);
                if (sel < cnt) {
                    float2 f = __half22float2(g_y1[(size_t)j * 16 + l]);
                    ax += f.x; ay += f.y;
                }
            }
        }
        ax += __shfl_xor_sync(0xffffffffu, ax, 16);
        ay += __shfl_xor_sync(0xffffffffu, ay, 16);
        if (half == 0) {
            float2 s = __half22float2(g_y1[(size_t)n * 16 + l]);
            float d = __ldg(&g_dinv[n]);
            g_a1[(size_t)n * 16 + l] = __floats2half2_rn(d * (ax + s.x), d * (ay + s.y));
        }
    }
}

// ---------------- CSR aggregate, 64-feat version (layer 2) ----------------
__global__ __launch_bounds__(256) void agg2_kernel() {
    int warp = blockIdx.x * 8 + (threadIdx.x >> 5);
    int lane = threadIdx.x & 31;
#pragma unroll 1
    for (int rep = 0; rep < 8; rep++) {
        int n = warp * 8 + rep;
        int rs = __ldg(&g_rowstart[n]);
        int deg = __ldg(&g_degi[n]);
        float ax = 0.f, ay = 0.f;
        for (int base = 0; base < deg; base += 32) {
            int rem = deg - base;
            int cnt = rem < 32 ? rem : 32;
            int idx = (lane < cnt) ? __ldg(&g_srt[rs + base + lane]) : 0;
            int p = 0;
            for (; p + 8 <= cnt; p += 8) {
                int j0 = __shfl_sync(0xffffffffu, idx, p + 0);
                int j1 = __shfl_sync(0xffffffffu, idx, p + 1);
                int j2 = __shfl_sync(0xffffffffu, idx, p + 2);
                int j3 = __shfl_sync(0xffffffffu, idx, p + 3);
                int j4 = __shfl_sync(0xffffffffu, idx, p + 4);
                int j5 = __shfl_sync(0xffffffffu, idx, p + 5);
                int j6 = __shfl_sync(0xffffffffu, idx, p + 6);
                int j7 = __shfl_sync(0xffffffffu, idx, p + 7);
                float2 f0 = __half22float2(g_y2[(size_t)j0 * 32 + lane]);
                float2 f1 = __half22float2(g_y2[(size_t)j1 * 32 + lane]);
                float2 f2 = __half22float2(g_y2[(size_t)j2 * 32 + lane]);
                float2 f3 = __half22float2(g_y2[(size_t)j3 * 32 + lane]);
                float2 f4 = __half22float2(g_y2[(size_t)j4 * 32 + lane]);
                float2 f5 = __half22float2(g_y2[(size_t)j5 * 32 + lane]);
                float2 f6 = __half22float2(g_y2[(size_t)j6 * 32 + lane]);
                float2 f7 = __half22float2(g_y2[(size_t)j7 * 32 + lane]);
                ax += ((f0.x + f1.x) + (f2.x + f3.x)) + ((f4.x + f5.x) + (f6.x + f7.x));
                ay += ((f0.y + f1.y) + (f2.y + f3.y)) + ((f4.y + f5.y) + (f6.y + f7.y));
            }
            for (; p < cnt; p++) {
                int j = __shfl_sync(0xffffffffu, idx, p);
                float2 f = __half22float2(g_y2[(size_t)j * 32 + lane]);
                ax += f.x; ay += f.y;
            }
        }
        float2 s = __half22float2(g_y2[(size_t)n * 32 + lane]);
        float d = __ldg(&g_dinv[n]);
        g_a2[(size_t)n * 32 + lane] = __floats2half2_rn(d * (ax + s.x), d * (ay + s.y));
    }
}

// ---------------- GEMM: z = a @ W + b ; fused BN stats ----------------
// K = input feats (32 or 64); 128 threads = 128 nodes per block.
template <int K>
__global__ __launch_bounds__(128) void xw_kernel(const __half2* __restrict__ av,
                                                 __half2* __restrict__ zv,
                                                 const float* __restrict__ W,
                                                 const float* __restrict__ b,
                                                 float* __restrict__ sArr,
                                                 float* __restrict__ qArr) {
    __shared__ __align__(16) float sW[K * HID];
    __shared__ __half2 sOut[128][33];
    __shared__ float ps[4][64], pq[4][64];
    int tid = threadIdx.x;
    for (int i = tid; i < K * HID; i += 128) sW[i] = W[i];
    __syncthreads();
    int n = blockIdx.x * 128 + tid;
    float in[K];
    {
        const uint4* r = (const uint4*)(av + (size_t)n * (K / 2));
#pragma unroll
        for (int q = 0; q < K / 8; q++) {
            uint4 u = __ldg(r + q);
            unsigned uu[4] = {u.x, u.y, u.z, u.w};
#pragma unroll
            for (int m = 0; m < 4; m++) {
                float2 f = __half22float2(*(__half2*)&uu[m]);
                in[8 * q + 2 * m + 0] = f.x;
                in[8 * q + 2 * m + 1] = f.y;
            }
        }
    }
#pragma unroll 1
    for (int jb = 0; jb < 4; jb++) {
        unsigned long long acc[8];
#pragma unroll
        for (int m = 0; m < 8; m++) acc[m] = 0ull;
#pragma unroll 4
        for (int k = 0; k < K; k++) {
            unsigned long long xp;
            asm("mov.b64 %0, {%1, %1};" : "=l"(xp) : "r"(__float_as_uint(in[k])));
            const ulonglong2* wp = (const ulonglong2*)(sW + k * HID + jb * 16);
            ulonglong2 w01 = wp[0], w23 = wp[1], w45 = wp[2], w67 = wp[3];
            acc[0] = ffma2(xp, w01.x, acc[0]);
            acc[1] = ffma2(xp, w01.y, acc[1]);
            acc[2] = ffma2(xp, w23.x, acc[2]);
            acc[3] = ffma2(xp, w23.y, acc[3]);
            acc[4] = ffma2(xp, w45.x, acc[4]);
            acc[5] = ffma2(xp, w45.y, acc[5]);
            acc[6] = ffma2(xp, w67.x, acc[6]);
            acc[7] = ffma2(xp, w67.y, acc[7]);
        }
#pragma unroll
        for (int m = 0; m < 8; m++) {
            float lo, hi;
            asm("mov.b64 {%0, %1}, %2;" : "=f"(lo), "=f"(hi) : "l"(acc[m]));
            int f0 = jb * 16 + 2 * m;
            sOut[tid][jb * 8 + m] = __floats2half2_rn(lo + __ldg(b + f0),
                                                      hi + __ldg(b + f0 + 1));
        }
    }
    __syncthreads();
    // coalesced write out
    unsigned* dst = (unsigned*)(zv + (size_t)blockIdx.x * 128 * 32);
    const unsigned* srcBase = (const unsigned*)sOut;
#pragma unroll
    for (int i = tid; i < 4096; i += 128) {
        int node = i >> 5, c = i & 31;
        dst[i] = srcBase[node * 33 + c];
    }
    // BN stats: thread (part, c) sums feature pair c over nodes part*32..+31
    {
        int c = tid & 31, part = tid >> 5;
        float s0 = 0.f, s1 = 0.f, q0 = 0.f, q1 = 0.f;
#pragma unroll 4
        for (int m = 0; m < 32; m++) {
            float2 f = __half22float2(sOut[part * 32 + m][c]);
            s0 += f.x; s1 += f.y; q0 += f.x * f.x; q1 += f.y * f.y;
        }
        ps[part][2 * c] = s0; ps[part][2 * c + 1] = s1;
        pq[part][2 * c] = q0; pq[part][2 * c + 1] = q1;
    }
    __syncthreads();
    if (tid < 64) {
        float s = ps[0][tid] + ps[1][tid] + ps[2][tid] + ps[3][tid];
        float q = pq[0][tid] + pq[1][tid] + pq[2][tid] + pq[3][tid];
        redf(sArr + tid, s);
        redf(qArr + tid, q);
    }
}

// ---------------- prep2: y2 = fp16(dinv * relu(bn1(z1))) ----------------
__global__ __launch_bounds__(256) void prep2_kernel(const float* __restrict__ gamma,
                                                    const float* __restrict__ beta) {
    __shared__ float sc[HID], sh[HID];
    int tid = threadIdx.x;
    if (tid < HID) {
        const float inv_n = 1.0f / (float)N_NODES;
        float mu = g_s1[tid] * inv_n;
        float var = g_q1[tid] * inv_n - mu * mu;
        float rstd = rsqrtf(var + BN_EPS);
        float s = rstd * __ldg(gamma + tid);
        sc[tid] = s;
        sh[tid] = __ldg(beta + tid) - mu * s;
    }
    __syncthreads();
    int i4 = blockIdx.x * 256 + tid;          // over N_NODES*8 uint4s
    int n = i4 >> 3;
    int fb = (i4 & 7) * 8;                    // first feat of this uint4
    float d = __ldg(&g_dinv[n]);
    uint4 u = *((const uint4*)g_z1 + i4);
    unsigned uu[4] = {u.x, u.y, u.z, u.w};
    uint4 o;
    unsigned* oo = (unsigned*)&o;
#pragma unroll
    for (int m = 0; m < 4; m++) {
        float2 f = __half22float2(*(__half2*)&uu[m]);
        int f0 = fb + 2 * m;
        float y0 = fmaxf(f.x * sc[f0] + sh[f0], 0.f) * d;
        float y1 = fmaxf(f.y * sc[f0 + 1] + sh[f0 + 1], 0.f) * d;
        __half2 h = __floats2half2_rn(y0, y1);
        oo[m] = *(unsigned*)&h;
    }
    *((uint4*)g_y2 + i4) = o;
}

// ---------------- pooling: mean over graph of relu(bn2(z2)) ----------------
__global__ __launch_bounds__(256) void pool_kernel(const float* __restrict__ gamma,
                                                   const float* __restrict__ beta) {
    int t = blockIdx.x * 256 + threadIdx.x;   // 32768 threads
    int g = t >> 5, j2 = t & 31;
    int s = g_start[g], e = g_start[g + 1];
    int c = e - s;
    const float inv_n = 1.0f / (float)N_NODES;
    int f0 = 2 * j2, f1 = 2 * j2 + 1;
    float mu0 = g_s2[f0] * inv_n, mu1 = g_s2[f1] * inv_n;
    float v0 = g_q2[f0] * inv_n - mu0 * mu0;
    float v1 = g_q2[f1] * inv_n - mu1 * mu1;
    float sc0 = rsqrtf(v0 + BN_EPS) * __ldg(gamma + f0);
    float sc1 = rsqrtf(v1 + BN_EPS) * __ldg(gamma + f1);
    float sh0 = __ldg(beta + f0) - mu0 * sc0;
    float sh1 = __ldg(beta + f1) - mu1 * sc1;
    float s0 = 0.f, s1 = 0.f;
    int i = s;
    for (; i + 4 <= e; i += 4) {
        float2 f0v = __half22float2(g_z2[(size_t)(i + 0) * 32 + j2]);
        float2 f1v = __half22float2(g_z2[(size_t)(i + 1) * 32 + j2]);
        float2 f2v = __half22float2(g_z2[(size_t)(i + 2) * 32 + j2]);
        float2 f3v = __half22float2(g_z2[(size_t)(i + 3) * 32 + j2]);
        s0 += fmaxf(f0v.x * sc0 + sh0, 0.f) + fmaxf(f1v.x * sc0 + sh0, 0.f)
            + fmaxf(f2v.x * sc0 + sh0, 0.f) + fmaxf(f3v.x * sc0 + sh0, 0.f);
        s1 += fmaxf(f0v.y * sc1 + sh1, 0.f) + fmaxf(f1v.y * sc1 + sh1, 0.f)
            + fmaxf(f2v.y * sc1 + sh1, 0.f) + fmaxf(f3v.y * sc1 + sh1, 0.f);
    }
    for (; i < e; i++) {
        float2 f = __half22float2(g_z2[(size_t)i * 32 + j2]);
        s0 += fmaxf(f.x * sc0 + sh0, 0.f);
        s1 += fmaxf(f.y * sc1 + sh1, 0.f);
    }
    float inv = (c > 0) ? 1.0f / (float)c : 0.f;
    *(float2*)(g_pooled + (size_t)g * HID + 2 * j2) = make_float2(s0 * inv, s1 * inv);
}

// ---------------- final MLP heads (one warp per graph) ----------------
__global__ __launch_bounds__(256) void mlp_kernel(
    const float* __restrict__ gf,
    const float* __restrict__ Wo1, const float* __restrict__ bo1,
    const float* __restrict__ Wo2, const float* __restrict__ bo2,
    const float* __restrict__ Wb1, const float* __restrict__ bb1,
    const float* __restrict__ Wb2, const float* __restrict__ bb2,
    float* __restrict__ out) {
    int warp = (blockIdx.x * 256 + threadIdx.x) >> 5;
    int lane = threadIdx.x & 31;
    if (warp >= N_GRAPHS) return;
    int g = warp;
    float hO = bo1[lane], hB = bb1[lane];
#pragma unroll 4
    for (int i = 0; i < HID + G_FEAT; i++) {
        float ci = (i < HID) ? g_pooled[(size_t)g * HID + i]
                             : gf[(size_t)g * G_FEAT + (i - HID)];
        hO += ci * Wo1[i * 32 + lane];
        hB += ci * Wb1[i * 32 + lane];
    }
    hO = fmaxf(hO, 0.f);
    hB = fmaxf(hB, 0.f);
    float vO = hO * Wo2[lane];
    float vB = hB * Wb2[lane];
#pragma unroll
    for (int off = 16; off; off >>= 1) {
        vO += __shfl_down_sync(0xffffffffu, vO, off);
        vB += __shfl_down_sync(0xffffffffu, vB, off);
    }
    if (lane == 0) {
        out[g] = vO + bo2[0];
        out[N_GRAPHS + g] = vB + bb2[0];
    }
}

// ---------------- launch ----------------
extern "C" void kernel_launch(void* const* d_in, const int* in_sizes, int n_in,
                              void* d_out, int out_size) {
    const float* x      = (const float*)d_in[0];
    const int*   ei     = (const int*)  d_in[1];
    const int*   batch  = (const int*)  d_in[2];
    const float* gfeat  = (const float*)d_in[3];
    const float* W1     = (const float*)d_in[4];
    const float* b1     = (const float*)d_in[5];
    const float* gamma1 = (const float*)d_in[6];
    const float* beta1  = (const float*)d_in[7];
    const float* W2     = (const float*)d_in[8];
    const float* b2     = (const float*)d_in[9];
    const float* gamma2 = (const float*)d_in[10];
    const float* beta2  = (const float*)d_in[11];
    const float* Wo1    = (const float*)d_in[12];
    const float* bo1    = (const float*)d_in[13];
    const float* Wo2    = (const float*)d_in[14];
    const float* bo2    = (const float*)d_in[15];
    const float* Wb1    = (const float*)d_in[16];
    const float* bb1    = (const float*)d_in[17];
    const float* Wb2    = (const float*)d_in[18];
    const float* bb2    = (const float*)d_in[19];
    float* out = (float*)d_out;

    float* s1; float* q1; float* s2; float* q2;
    cudaGetSymbolAddress((void**)&s1, g_s1);
    cudaGetSymbolAddress((void**)&q1, g_q1);
    cudaGetSymbolAddress((void**)&s2, g_s2);
    cudaGetSymbolAddress((void**)&q2, g_q2);
    __half2* a1; __half2* z1; __half2* a2; __half2* z2;
    cudaGetSymbolAddress((void**)&a1, g_a1);
    cudaGetSymbolAddress((void**)&z1, g_z1);
    cudaGetSymbolAddress((void**)&a2, g_a2);
    cudaGetSymbolAddress((void**)&z2, g_z2);

    zero_kernel<<<512, 256>>>(batch);
    deg_kernel<<<2048, 256>>>(ei);
    scanA_kernel<<<512, 256>>>();
    scanB_kernel<<<1, 512>>>();
    scanC_kernel<<<512, 256>>>(x);
    bucket_kernel<<<2048, 256>>>(ei);

    // ---- layer 1 (aggregate raw features, then GEMM) ----
    agg1_kernel<<<2048, 256>>>();
    xw_kernel<F_IN><<<N_NODES / 128, 128>>>(a1, z1, W1, b1, s1, q1);

    // ---- layer 2 ----
    prep2_kernel<<<4096, 256>>>(gamma1, beta1);
    agg2_kernel<<<2048, 256>>>();
    xw_kernel<HID><<<N_NODES / 128, 128>>>(a2, z2, W2, b2, s2, q2);

    // ---- pooling (BN2+relu fused) + heads ----
    pool_kernel<<<128, 256>>>(gamma2, beta2);
    mlp_kernel<<<N_GRAPHS / 8, 256>>>(gfeat, Wo1, bo1, Wo2, bo2,
                                      Wb1, bb1, Wb2, bb2, out);
}